// round 7
// baseline (speedup 1.0000x reference)
#include <cuda_runtime.h>

#define DIM 128
#define N 512
#define HEADS 4
#define DH 32
#define HID 128
#define IND 5
#define KSPLIT 8
#define ATTN_SCALE 0.17677669529663687f   // 32^-0.5

// Scratch (allocation-free rule: __device__ globals). 256B-aligned (vector access).
__device__ __align__(256) float g_qkv[3 * HID * N];     // [384][512] q|k|v
__device__ __align__(256) float g_A2[HEADS * IND * N];  // [h][c][i]
__device__ __align__(256) float g_B3[HEADS * IND * N];  // [h][c][j]
__device__ __align__(256) float g_W4[HEADS * 25];       // [h][c*5+cp]
__device__ __align__(256) float g_qk[HEADS * N * N];    // [h][i][j]: qk, then probs (in-place)
__device__ __align__(256) float g_avp[KSPLIT * HID * N];// partial attn@v

// ---------------------------------------------------------------------------
// K1: tiled GEMM qkv = w_qkv (384x128) @ x (128x512). TM=32,TN=64,TK=16.
// ---------------------------------------------------------------------------
__global__ __launch_bounds__(256) void k_qkv(const float* __restrict__ A,
                                             const float* __restrict__ B,
                                             float* __restrict__ C) {
    __shared__ float As[16][32];
    __shared__ float Bs[16][64];
    const int n0 = blockIdx.x * 64;
    const int m0 = blockIdx.y * 32;
    const int t  = threadIdx.x;
    const int tx = t & 15, ty = t >> 4;

    float acc[2][4] = {};
    for (int k0 = 0; k0 < DIM; k0 += 16) {
#pragma unroll
        for (int idx = t; idx < 512; idx += 256) {
            int kk = idx & 15, m = idx >> 4;
            As[kk][m] = A[(m0 + m) * DIM + k0 + kk];
        }
#pragma unroll
        for (int idx = t; idx < 1024; idx += 256) {
            int n = idx & 63, kk = idx >> 6;
            Bs[kk][n] = B[(k0 + kk) * N + n0 + n];
        }
        __syncthreads();
#pragma unroll
        for (int kk = 0; kk < 16; kk++) {
            float2 a = ((const float2*)&As[kk][0])[ty];
            float4 b = ((const float4*)&Bs[kk][0])[tx];
            acc[0][0] = fmaf(a.x, b.x, acc[0][0]);
            acc[0][1] = fmaf(a.x, b.y, acc[0][1]);
            acc[0][2] = fmaf(a.x, b.z, acc[0][2]);
            acc[0][3] = fmaf(a.x, b.w, acc[0][3]);
            acc[1][0] = fmaf(a.y, b.x, acc[1][0]);
            acc[1][1] = fmaf(a.y, b.y, acc[1][1]);
            acc[1][2] = fmaf(a.y, b.z, acc[1][2]);
            acc[1][3] = fmaf(a.y, b.w, acc[1][3]);
        }
        __syncthreads();
    }
#pragma unroll
    for (int r = 0; r < 2; r++) {
        int m = m0 + ty * 2 + r;
        float* cp = &C[m * N + n0 + tx * 4];
        cp[0] = acc[r][0]; cp[1] = acc[r][1]; cp[2] = acc[r][2]; cp[3] = acc[r][3];
    }
}

// ---------------------------------------------------------------------------
// K2: qk GEMM (z<4) + A2/B3/W4 side-work (z==4). 256 threads.
// ---------------------------------------------------------------------------
__global__ __launch_bounds__(256) void k_qk(const float* __restrict__ w_ind) {
    const int t = threadIdx.x;

    if (blockIdx.z == 4) {
        const int u = blockIdx.y * 8 + blockIdx.x;   // 0..63
        if (u < 40) {
            const bool isA = u < 20;
            const int v = isA ? u : u - 20;
            const int h = v / 5, c = v % 5;
            __shared__ float ws[DH];
            if (t < DH)
                ws[t] = isA ? w_ind[(HID + h * DH + t) * IND + c]  // A2: q . wk_ind
                            : w_ind[(h * DH + t) * IND + c];       // B3: k . wq_ind
            __syncthreads();
            const float* src = g_qkv + (isA ? (h * DH) * N : (HID + h * DH) * N);
            for (int ii = t; ii < N; ii += 256) {
                float acc = 0.f;
#pragma unroll
                for (int d = 0; d < DH; d++)
                    acc = fmaf(src[d * N + ii], ws[d], acc);
                (isA ? g_A2 : g_B3)[(h * IND + c) * N + ii] = acc;
            }
        } else if (u == 40) {
            if (t < HEADS * 25) {
                int h = t / 25, c = (t % 25) / 5, cp = t % 5;
                float acc = 0.f;
#pragma unroll
                for (int d = 0; d < DH; d++)
                    acc = fmaf(w_ind[(h * DH + d) * IND + c],
                               w_ind[(HID + h * DH + d) * IND + cp], acc);
                g_W4[t] = acc;
            }
        }
        return;
    }

    // ---- qk tile: g_qk[h][i][j] = sum_d q[h,d,i]*k[h,d,j] ----
    __shared__ float qs[DH][64];
    __shared__ float ks[DH][64];
    const int j0 = blockIdx.x * 64;
    const int i0 = blockIdx.y * 64;
    const int h  = blockIdx.z;
    const int tx = t & 15, ty = t >> 4;

    const float* qb = g_qkv + (h * DH) * N;
    const float* kb = g_qkv + (HID + h * DH) * N;
#pragma unroll
    for (int idx = t; idx < DH * 64; idx += 256) {
        int d = idx >> 6, c = idx & 63;
        qs[d][c] = qb[d * N + i0 + c];
        ks[d][c] = kb[d * N + j0 + c];
    }
    __syncthreads();

    float acc[4][4] = {};
#pragma unroll
    for (int d = 0; d < DH; d++) {
        float4 qa = ((const float4*)&qs[d][0])[ty];
        float4 kv = ((const float4*)&ks[d][0])[tx];
        acc[0][0] = fmaf(qa.x, kv.x, acc[0][0]);
        acc[0][1] = fmaf(qa.x, kv.y, acc[0][1]);
        acc[0][2] = fmaf(qa.x, kv.z, acc[0][2]);
        acc[0][3] = fmaf(qa.x, kv.w, acc[0][3]);
        acc[1][0] = fmaf(qa.y, kv.x, acc[1][0]);
        acc[1][1] = fmaf(qa.y, kv.y, acc[1][1]);
        acc[1][2] = fmaf(qa.y, kv.z, acc[1][2]);
        acc[1][3] = fmaf(qa.y, kv.w, acc[1][3]);
        acc[2][0] = fmaf(qa.z, kv.x, acc[2][0]);
        acc[2][1] = fmaf(qa.z, kv.y, acc[2][1]);
        acc[2][2] = fmaf(qa.z, kv.z, acc[2][2]);
        acc[2][3] = fmaf(qa.z, kv.w, acc[2][3]);
        acc[3][0] = fmaf(qa.w, kv.x, acc[3][0]);
        acc[3][1] = fmaf(qa.w, kv.y, acc[3][1]);
        acc[3][2] = fmaf(qa.w, kv.z, acc[3][2]);
        acc[3][3] = fmaf(qa.w, kv.w, acc[3][3]);
    }
    float* cb = g_qk + ((size_t)h * N) * N;
#pragma unroll
    for (int r = 0; r < 4; r++) {
        int i = i0 + ty * 4 + r;
        ((float4*)&cb[(size_t)i * N + j0])[tx] =
            make_float4(acc[r][0], acc[r][1], acc[r][2], acc[r][3]);
    }
}

// ---------------------------------------------------------------------------
// K3: sim + softmax for ALL 4 heads, one block per i, float2 per thread.
// 256 threads (8 warps); probs written in place over g_qk.
// ---------------------------------------------------------------------------
__global__ __launch_bounds__(256) void k_sim(const float* __restrict__ indicator) {
    const int i = blockIdx.x;
    const int t = threadIdx.x;          // owns j = 2t, 2t+1
    const int warp = t >> 5, lane = t & 31;

    __shared__ float a2s[HEADS][IND];
    __shared__ float w4s[HEADS][25];
    __shared__ float red[HEADS][8];

    if (t < HEADS * IND)
        a2s[t / IND][t % IND] = g_A2[t * N + i];
    else if (t < HEADS * IND + HEADS * 25) {
        int u = t - HEADS * IND;
        w4s[u / 25][u % 25] = g_W4[u];
    }
    __syncthreads();

    float2 iv[IND];
#pragma unroll
    for (int c = 0; c < IND; c++)
        iv[c] = *(const float2*)(indicator + ((size_t)c * N + i) * N + 2 * t);

    float2 sim[HEADS];
#pragma unroll
    for (int h = 0; h < HEADS; h++) {
        float2 qk = *(const float2*)(g_qk + ((size_t)h * N + i) * N + 2 * t);
        float linx = 0.f, liny = 0.f, quadx = 0.f, quady = 0.f;
#pragma unroll
        for (int c = 0; c < IND; c++) {
            float2 b3 = *(const float2*)(g_B3 + (h * IND + c) * N + 2 * t);
            float a2 = a2s[h][c];
            linx = fmaf(iv[c].x, a2 + b3.x, linx);
            liny = fmaf(iv[c].y, a2 + b3.y, liny);
            float tx2 = 0.f, ty2 = 0.f;
#pragma unroll
            for (int cp = 0; cp < IND; cp++) {
                float w = w4s[h][c * 5 + cp];
                tx2 = fmaf(w, iv[cp].x, tx2);
                ty2 = fmaf(w, iv[cp].y, ty2);
            }
            quadx = fmaf(iv[c].x, tx2, quadx);
            quady = fmaf(iv[c].y, ty2, quady);
        }
        sim[h].x = ATTN_SCALE * (qk.x + linx + quadx);
        sim[h].y = ATTN_SCALE * (qk.y + liny + quady);
    }

    // --- max reduce ---
    float m4[HEADS];
#pragma unroll
    for (int h = 0; h < HEADS; h++) m4[h] = fmaxf(sim[h].x, sim[h].y);
#pragma unroll
    for (int off = 16; off; off >>= 1)
#pragma unroll
        for (int h = 0; h < HEADS; h++)
            m4[h] = fmaxf(m4[h], __shfl_xor_sync(0xffffffffu, m4[h], off));
    if (lane == 0)
#pragma unroll
        for (int h = 0; h < HEADS; h++) red[h][warp] = m4[h];
    __syncthreads();
    float gmax[HEADS];
#pragma unroll
    for (int h = 0; h < HEADS; h++) {
        float g = red[h][0];
#pragma unroll
        for (int w = 1; w < 8; w++) g = fmaxf(g, red[h][w]);
        gmax[h] = g;
    }
    __syncthreads();

    // --- exp + sum reduce ---
    float2 e[HEADS];
    float ss[HEADS];
#pragma unroll
    for (int h = 0; h < HEADS; h++) {
        e[h].x = __expf(sim[h].x - gmax[h]);
        e[h].y = __expf(sim[h].y - gmax[h]);
        ss[h] = e[h].x + e[h].y;
    }
#pragma unroll
    for (int off = 16; off; off >>= 1)
#pragma unroll
        for (int h = 0; h < HEADS; h++)
            ss[h] += __shfl_xor_sync(0xffffffffu, ss[h], off);
    if (lane == 0)
#pragma unroll
        for (int h = 0; h < HEADS; h++) red[h][warp] = ss[h];
    __syncthreads();
#pragma unroll
    for (int h = 0; h < HEADS; h++) {
        float g = 0.f;
#pragma unroll
        for (int w = 0; w < 8; w++) g += red[h][w];
        float inv = 1.0f / g;
        float2 p;
        p.x = e[h].x * inv; p.y = e[h].y * inv;
        *(float2*)(g_qk + ((size_t)h * N + i) * N + 2 * t) = p;
    }
}

// ---------------------------------------------------------------------------
// K4: partial attn@v GEMM. avp[z][h*32+d][i] = sum_{j in split z} P[h,i,j]*v[h,d,j]
// grid (N/64, HEADS, KSPLIT), 256 threads, tile M=32(d) x N=64(i), rtile 2x4.
// ---------------------------------------------------------------------------
__global__ __launch_bounds__(256) void k_av() {
    __shared__ float Ps[32][65];   // [kk][n]
    __shared__ float Vs[32][33];   // [kk][m]
    const int i0 = blockIdx.x * 64;
    const int h  = blockIdx.y;
    const int z  = blockIdx.z;
    const int js = z * (N / KSPLIT);
    const int t  = threadIdx.x;
    const int tx = t & 15;         // n quad (4*tx)
    const int ty = t >> 4;         // m pair (2*ty, 0..15 -> m 0..31)

    const float* P = g_qk + (size_t)h * N * N;
    const float* V = g_qkv + (2 * HID + h * DH) * N;

    float acc[2][4] = {};
    for (int j0 = js; j0 < js + N / KSPLIT; j0 += 32) {
#pragma unroll
        for (int r = 0; r < 8; r++) {           // Ps: 32x64 = 2048
            int idx = t + r * 256;
            int kk = idx & 31, n = idx >> 5;
            Ps[kk][n] = P[(size_t)(i0 + n) * N + j0 + kk];
        }
#pragma unroll
        for (int r = 0; r < 4; r++) {           // Vs: 32x32 = 1024
            int idx = t + r * 256;
            int kk = idx & 31, m = idx >> 5;
            Vs[kk][m] = V[m * N + j0 + kk];
        }
        __syncthreads();
#pragma unroll
        for (int kk = 0; kk < 32; kk++) {
            float v0 = Vs[kk][2 * ty + 0], v1 = Vs[kk][2 * ty + 1];
            float p0 = Ps[kk][4 * tx + 0], p1 = Ps[kk][4 * tx + 1];
            float p2 = Ps[kk][4 * tx + 2], p3 = Ps[kk][4 * tx + 3];
            acc[0][0] = fmaf(v0, p0, acc[0][0]);
            acc[0][1] = fmaf(v0, p1, acc[0][1]);
            acc[0][2] = fmaf(v0, p2, acc[0][2]);
            acc[0][3] = fmaf(v0, p3, acc[0][3]);
            acc[1][0] = fmaf(v1, p0, acc[1][0]);
            acc[1][1] = fmaf(v1, p1, acc[1][1]);
            acc[1][2] = fmaf(v1, p2, acc[1][2]);
            acc[1][3] = fmaf(v1, p3, acc[1][3]);
        }
        __syncthreads();
    }
    float* outp = g_avp + (size_t)z * HID * N;
#pragma unroll
    for (int r = 0; r < 2; r++) {
        int m = 2 * ty + r;
        float* cp = &outp[(h * DH + m) * N + i0 + 4 * tx];
        cp[0] = acc[r][0]; cp[1] = acc[r][1]; cp[2] = acc[r][2]; cp[3] = acc[r][3];
    }
}

// ---------------------------------------------------------------------------
// K5: out = w_out (128x128) @ (sum_z avp[z]) (128x512) + b_out
// grid (16, 4): TM=32, TN=32; 256 threads, 2x2 register tile.
// ---------------------------------------------------------------------------
__global__ __launch_bounds__(256) void k_proj(const float* __restrict__ A,
                                              const float* __restrict__ bias,
                                              float* __restrict__ C) {
    __shared__ float As[16][32];
    __shared__ float Bs[16][36];
    const int n0 = blockIdx.x * 32;
    const int m0 = blockIdx.y * 32;
    const int t  = threadIdx.x;
    const int tx = t & 15, ty = t >> 4;

    float acc[2][2] = {};
    for (int k0 = 0; k0 < HID; k0 += 16) {
#pragma unroll
        for (int r = 0; r < 2; r++) {            // As: 16x32 = 512
            int idx = t + r * 256;
            int kk = idx & 15, m = idx >> 4;
            As[kk][m] = A[(m0 + m) * HID + k0 + kk];
        }
#pragma unroll
        for (int r = 0; r < 2; r++) {            // Bs: 16x32 = 512 (z-reduced)
            int idx = t + r * 256;
            int n = idx & 31, kk = idx >> 5;
            float v = 0.f;
#pragma unroll
            for (int zz = 0; zz < KSPLIT; zz++)
                v += g_avp[((size_t)zz * HID + k0 + kk) * N + n0 + n];
            Bs[kk][n] = v;
        }
        __syncthreads();
#pragma unroll
        for (int kk = 0; kk < 16; kk++) {
            float2 a = ((const float2*)&As[kk][0])[ty];
            float2 b = ((const float2*)&Bs[kk][0])[tx];
            acc[0][0] = fmaf(a.x, b.x, acc[0][0]);
            acc[0][1] = fmaf(a.x, b.y, acc[0][1]);
            acc[1][0] = fmaf(a.y, b.x, acc[1][0]);
            acc[1][1] = fmaf(a.y, b.y, acc[1][1]);
        }
        __syncthreads();
    }
#pragma unroll
    for (int r = 0; r < 2; r++) {
        int m = m0 + ty * 2 + r;
        float bv = bias[m];
        float* cp = &C[m * N + n0 + tx * 2];
        cp[0] = acc[r][0] + bv;
        cp[1] = acc[r][1] + bv;
    }
}

// ---------------------------------------------------------------------------
extern "C" void kernel_launch(void* const* d_in, const int* in_sizes, int n_in,
                              void* d_out, int out_size) {
    const float* x         = (const float*)d_in[0];   // (1,128,512)
    const float* indicator = (const float*)d_in[1];   // (1,5,512,512)
    const float* w_qkv     = (const float*)d_in[2];   // (384,128)
    const float* w_ind     = (const float*)d_in[3];   // (256,5)
    const float* w_out     = (const float*)d_in[4];   // (128,128)
    const float* b_out     = (const float*)d_in[5];   // (128,)
    float* out             = (float*)d_out;           // (1,128,512)

    float* qkv;  cudaGetSymbolAddress((void**)&qkv, g_qkv);

    k_qkv<<<dim3(8, 12), 256>>>(w_qkv, x, qkv);        // qkv = w_qkv @ x
    k_qk<<<dim3(8, 8, 5), 256>>>(w_ind);               // raw q.k  +  A2/B3/W4
    k_sim<<<N, 256>>>(indicator);                      // sim+softmax -> probs (in place)
    k_av<<<dim3(8, HEADS, KSPLIT), 256>>>();           // partial attn@v
    k_proj<<<dim3(16, 4), 256>>>(w_out, b_out, out);   // w_out @ sum(avp) + b
}

// round 8
// speedup vs baseline: 1.3393x; 1.3393x over previous
#include <cuda_runtime.h>

#define DIM 128
#define N 512
#define HEADS 4
#define DH 32
#define HID 128
#define IND 5
#define ATTN_SCALE 0.17677669529663687f   // 32^-0.5

// Scratch (allocation-free rule: __device__ globals). 256B-aligned (vector access).
__device__ __align__(256) float g_qkv[3 * HID * N];     // [384][512] q|k|v
__device__ __align__(256) float g_A2[HEADS * IND * N];  // [h][c][i]
__device__ __align__(256) float g_B3[HEADS * IND * N];  // [h][c][j]
__device__ __align__(256) float g_W4[HEADS * 25];       // [h][c*5+cp]
__device__ __align__(256) float g_qk[HEADS * N * N];    // [h][i][j] raw q.k

// ---------------------------------------------------------------------------
// K1: qkv = w_qkv (384x128) @ x (128x512), TM=32,TN=64,TK=16, 256 threads.
// Epilogue also computes A2 (q-blocks), B3 (k-blocks), W4 (block y=8,x=0).
// ---------------------------------------------------------------------------
__global__ __launch_bounds__(256) void k_qkv(const float* __restrict__ A,
                                             const float* __restrict__ B,
                                             const float* __restrict__ w_ind,
                                             float* __restrict__ C) {
    __shared__ float As[16][32];
    __shared__ float Bs[16][64];
    __shared__ float Cs[32][65];
    __shared__ float wsm[32][5];
    const int n0 = blockIdx.x * 64;
    const int m0 = blockIdx.y * 32;
    const int t  = threadIdx.x;
    const int tx = t & 15, ty = t >> 4;

    float acc[2][4] = {};
    for (int k0 = 0; k0 < DIM; k0 += 16) {
#pragma unroll
        for (int idx = t; idx < 512; idx += 256) {
            int kk = idx & 15, m = idx >> 4;
            As[kk][m] = A[(m0 + m) * DIM + k0 + kk];
        }
#pragma unroll
        for (int idx = t; idx < 1024; idx += 256) {
            int n = idx & 63, kk = idx >> 6;
            Bs[kk][n] = B[(k0 + kk) * N + n0 + n];
        }
        __syncthreads();
#pragma unroll
        for (int kk = 0; kk < 16; kk++) {
            float2 a = ((const float2*)&As[kk][0])[ty];
            float4 b = ((const float4*)&Bs[kk][0])[tx];
            acc[0][0] = fmaf(a.x, b.x, acc[0][0]);
            acc[0][1] = fmaf(a.x, b.y, acc[0][1]);
            acc[0][2] = fmaf(a.x, b.z, acc[0][2]);
            acc[0][3] = fmaf(a.x, b.w, acc[0][3]);
            acc[1][0] = fmaf(a.y, b.x, acc[1][0]);
            acc[1][1] = fmaf(a.y, b.y, acc[1][1]);
            acc[1][2] = fmaf(a.y, b.z, acc[1][2]);
            acc[1][3] = fmaf(a.y, b.w, acc[1][3]);
        }
        __syncthreads();
    }
    // write C and stage tile in smem
#pragma unroll
    for (int r = 0; r < 2; r++) {
        int m = ty * 2 + r;
        float* cp = &C[(m0 + m) * N + n0 + tx * 4];
        cp[0] = acc[r][0]; cp[1] = acc[r][1]; cp[2] = acc[r][2]; cp[3] = acc[r][3];
        Cs[m][tx * 4 + 0] = acc[r][0];
        Cs[m][tx * 4 + 1] = acc[r][1];
        Cs[m][tx * 4 + 2] = acc[r][2];
        Cs[m][tx * 4 + 3] = acc[r][3];
    }

    if (m0 < 2 * HID) {
        // A2 (q-blocks) / B3 (k-blocks): 64 cols x 5 coeffs, 32-deep dots
        const bool isQ = (m0 < HID);
        const int wbase = isQ ? (HID + m0) : (m0 - HID);   // wk rows for A2, wq rows for B3
        if (t < 160) wsm[t / 5][t % 5] = w_ind[(wbase + t / 5) * IND + (t % 5)];
        __syncthreads();
        const int h = (isQ ? m0 : m0 - HID) >> 5;
        float* dst = (isQ ? g_A2 : g_B3);
#pragma unroll
        for (int task = t; task < 320; task += 256) {
            int col = task & 63, c = task >> 6;
            float s = 0.f;
#pragma unroll
            for (int d = 0; d < DH; d++)
                s = fmaf(Cs[d][col], wsm[d][c], s);
            dst[(h * IND + c) * N + n0 + col] = s;
        }
    } else if (m0 == 2 * HID && n0 == 0) {
        // W4[h][c*5+cp] = sum_d wq[h,d,c] * wk[h,d,cp]
        if (t < HEADS * 25) {
            int h = t / 25, c = (t % 25) / 5, cp = t % 5;
            float s = 0.f;
#pragma unroll
            for (int d = 0; d < DH; d++)
                s = fmaf(w_ind[(h * DH + d) * IND + c],
                         w_ind[(HID + h * DH + d) * IND + cp], s);
            g_W4[t] = s;
        }
    }
}

// ---------------------------------------------------------------------------
// K2: g_qk[h][i][j] = sum_d q[h,d,i]*k[h,d,j].  64x64 tile, 4x4 rtile.
// ---------------------------------------------------------------------------
__global__ __launch_bounds__(256) void k_qk() {
    __shared__ float qs[DH][64];
    __shared__ float ks[DH][64];
    const int j0 = blockIdx.x * 64;
    const int i0 = blockIdx.y * 64;
    const int h  = blockIdx.z;
    const int t  = threadIdx.x;
    const int tx = t & 15, ty = t >> 4;

    const float* qb = g_qkv + (h * DH) * N;
    const float* kb = g_qkv + (HID + h * DH) * N;
#pragma unroll
    for (int idx = t; idx < DH * 64; idx += 256) {
        int d = idx >> 6, c = idx & 63;
        qs[d][c] = qb[d * N + i0 + c];
        ks[d][c] = kb[d * N + j0 + c];
    }
    __syncthreads();

    float acc[4][4] = {};
#pragma unroll
    for (int d = 0; d < DH; d++) {
        float4 qa = ((const float4*)&qs[d][0])[ty];
        float4 kv = ((const float4*)&ks[d][0])[tx];
        acc[0][0] = fmaf(qa.x, kv.x, acc[0][0]);
        acc[0][1] = fmaf(qa.x, kv.y, acc[0][1]);
        acc[0][2] = fmaf(qa.x, kv.z, acc[0][2]);
        acc[0][3] = fmaf(qa.x, kv.w, acc[0][3]);
        acc[1][0] = fmaf(qa.y, kv.x, acc[1][0]);
        acc[1][1] = fmaf(qa.y, kv.y, acc[1][1]);
        acc[1][2] = fmaf(qa.y, kv.z, acc[1][2]);
        acc[1][3] = fmaf(qa.y, kv.w, acc[1][3]);
        acc[2][0] = fmaf(qa.z, kv.x, acc[2][0]);
        acc[2][1] = fmaf(qa.z, kv.y, acc[2][1]);
        acc[2][2] = fmaf(qa.z, kv.z, acc[2][2]);
        acc[2][3] = fmaf(qa.z, kv.w, acc[2][3]);
        acc[3][0] = fmaf(qa.w, kv.x, acc[3][0]);
        acc[3][1] = fmaf(qa.w, kv.y, acc[3][1]);
        acc[3][2] = fmaf(qa.w, kv.z, acc[3][2]);
        acc[3][3] = fmaf(qa.w, kv.w, acc[3][3]);
    }
    float* cb = g_qk + ((size_t)h * N) * N;
#pragma unroll
    for (int r = 0; r < 4; r++) {
        int i = i0 + ty * 4 + r;
        ((float4*)&cb[(size_t)i * N + j0])[tx] =
            make_float4(acc[r][0], acc[r][1], acc[r][2], acc[r][3]);
    }
}

// ---------------------------------------------------------------------------
// K3: fused sim + softmax + attn@v + w_out projection.  One block per i,
// 256 threads; probs and av stay in smem.
// ---------------------------------------------------------------------------
__global__ __launch_bounds__(256) void k_fused(const float* __restrict__ indicator,
                                               const float* __restrict__ w_out,
                                               const float* __restrict__ b_out,
                                               float* __restrict__ out) {
    const int i = blockIdx.x;
    const int t = threadIdx.x;          // owns j = 2t, 2t+1
    const int warp = t >> 5, lane = t & 31;

    __shared__ float a2s[HEADS][IND];
    __shared__ float w4s[HEADS][25];
    __shared__ float red[HEADS][8];
    __shared__ __align__(16) float ps[HEADS][N];   // probs
    __shared__ __align__(16) float avs[HID];       // attn@v for this i

    if (t < HEADS * IND)
        a2s[t / IND][t % IND] = g_A2[t * N + i];
    else if (t < HEADS * IND + HEADS * 25) {
        int u = t - HEADS * IND;
        w4s[u / 25][u % 25] = g_W4[u];
    }
    __syncthreads();

    // ---- sim for all heads (float2 per thread) ----
    float2 iv[IND];
#pragma unroll
    for (int c = 0; c < IND; c++)
        iv[c] = *(const float2*)(indicator + ((size_t)c * N + i) * N + 2 * t);

    float2 sim[HEADS];
#pragma unroll
    for (int h = 0; h < HEADS; h++) {
        float2 qk = *(const float2*)(g_qk + ((size_t)h * N + i) * N + 2 * t);
        float linx = 0.f, liny = 0.f, quadx = 0.f, quady = 0.f;
#pragma unroll
        for (int c = 0; c < IND; c++) {
            float2 b3 = *(const float2*)(g_B3 + (h * IND + c) * N + 2 * t);
            float a2 = a2s[h][c];
            linx = fmaf(iv[c].x, a2 + b3.x, linx);
            liny = fmaf(iv[c].y, a2 + b3.y, liny);
            float tx2 = 0.f, ty2 = 0.f;
#pragma unroll
            for (int cp = 0; cp < IND; cp++) {
                float w = w4s[h][c * 5 + cp];
                tx2 = fmaf(w, iv[cp].x, tx2);
                ty2 = fmaf(w, iv[cp].y, ty2);
            }
            quadx = fmaf(iv[c].x, tx2, quadx);
            quady = fmaf(iv[c].y, ty2, quady);
        }
        sim[h].x = ATTN_SCALE * (qk.x + linx + quadx);
        sim[h].y = ATTN_SCALE * (qk.y + liny + quady);
    }

    // ---- softmax: max reduce ----
    float m4[HEADS];
#pragma unroll
    for (int h = 0; h < HEADS; h++) m4[h] = fmaxf(sim[h].x, sim[h].y);
#pragma unroll
    for (int off = 16; off; off >>= 1)
#pragma unroll
        for (int h = 0; h < HEADS; h++)
            m4[h] = fmaxf(m4[h], __shfl_xor_sync(0xffffffffu, m4[h], off));
    if (lane == 0)
#pragma unroll
        for (int h = 0; h < HEADS; h++) red[h][warp] = m4[h];
    __syncthreads();
    float gmax[HEADS];
#pragma unroll
    for (int h = 0; h < HEADS; h++) {
        float g = red[h][0];
#pragma unroll
        for (int w = 1; w < 8; w++) g = fmaxf(g, red[h][w]);
        gmax[h] = g;
    }
    __syncthreads();

    // ---- exp + sum reduce, write normalized probs to smem ----
    float2 e[HEADS];
    float ss[HEADS];
#pragma unroll
    for (int h = 0; h < HEADS; h++) {
        e[h].x = __expf(sim[h].x - gmax[h]);
        e[h].y = __expf(sim[h].y - gmax[h]);
        ss[h] = e[h].x + e[h].y;
    }
#pragma unroll
    for (int off = 16; off; off >>= 1)
#pragma unroll
        for (int h = 0; h < HEADS; h++)
            ss[h] += __shfl_xor_sync(0xffffffffu, ss[h], off);
    if (lane == 0)
#pragma unroll
        for (int h = 0; h < HEADS; h++) red[h][warp] = ss[h];
    __syncthreads();
#pragma unroll
    for (int h = 0; h < HEADS; h++) {
        float g = 0.f;
#pragma unroll
        for (int w = 0; w < 8; w++) g += red[h][w];
        float inv = 1.0f / g;
        float2 p;
        p.x = e[h].x * inv; p.y = e[h].y * inv;
        *(float2*)&ps[h][2 * t] = p;
    }
    __syncthreads();

    // ---- attn@v: 128 rows (h*32+d), each warp takes 16 rows ----
#pragma unroll
    for (int rr = 0; rr < 16; rr++) {
        int row = warp * 16 + rr;            // 0..127
        int h = row >> 5;
        const float4* vr = (const float4*)(g_qkv + (2 * HID + row) * N);
        const float4* pr = (const float4*)&ps[h][0];
        float acc = 0.f;
#pragma unroll
        for (int u = lane; u < N / 4; u += 32) {
            float4 v4 = vr[u];
            float4 p4 = pr[u];
            acc = fmaf(v4.x, p4.x, acc);
            acc = fmaf(v4.y, p4.y, acc);
            acc = fmaf(v4.z, p4.z, acc);
            acc = fmaf(v4.w, p4.w, acc);
        }
#pragma unroll
        for (int off = 16; off; off >>= 1)
            acc += __shfl_xor_sync(0xffffffffu, acc, off);
        if (lane == 0) avs[row] = acc;
    }
    __syncthreads();

    // ---- projection: out[o,i] = w_out[o,:] . avs + b_out[o] ----
#pragma unroll
    for (int rr = 0; rr < 16; rr++) {
        int o = warp * 16 + rr;              // 0..127
        float4 w4 = ((const float4*)(w_out + o * HID))[lane];
        float4 a4 = ((const float4*)avs)[lane];
        float acc = w4.x * a4.x + w4.y * a4.y + w4.z * a4.z + w4.w * a4.w;
#pragma unroll
        for (int off = 16; off; off >>= 1)
            acc += __shfl_xor_sync(0xffffffffu, acc, off);
        if (lane == 0) out[o * N + i] = acc + b_out[o];
    }
}

// ---------------------------------------------------------------------------
extern "C" void kernel_launch(void* const* d_in, const int* in_sizes, int n_in,
                              void* d_out, int out_size) {
    const float* x         = (const float*)d_in[0];   // (1,128,512)
    const float* indicator = (const float*)d_in[1];   // (1,5,512,512)
    const float* w_qkv     = (const float*)d_in[2];   // (384,128)
    const float* w_ind     = (const float*)d_in[3];   // (256,5)
    const float* w_out     = (const float*)d_in[4];   // (128,128)
    const float* b_out     = (const float*)d_in[5];   // (128,)
    float* out             = (float*)d_out;           // (1,128,512)

    float* qkv;  cudaGetSymbolAddress((void**)&qkv, g_qkv);

    k_qkv<<<dim3(8, 12), 256>>>(w_qkv, x, w_ind, qkv);    // qkv + A2/B3/W4
    k_qk<<<dim3(8, 8, 4), 256>>>();                        // raw q.k
    k_fused<<<N, 256>>>(indicator, w_out, b_out, out);     // sim+softmax+av+proj
}

// round 9
// speedup vs baseline: 1.4895x; 1.1121x over previous
#include <cuda_runtime.h>

#define DIM 128
#define N 512
#define HEADS 4
#define DH 32
#define HID 128
#define IND 5
#define ATTN_SCALE 0.17677669529663687f   // 32^-0.5

// Scratch (allocation-free rule: __device__ globals). 256B-aligned (vector access).
__device__ __align__(256) float g_qkv[3 * HID * N];     // [384][512] q|k|v
__device__ __align__(256) float g_A2[HEADS * IND * N];  // [h][c][i]
__device__ __align__(256) float g_B3[HEADS * IND * N];  // [h][c][j]
__device__ __align__(256) float g_W4[HEADS * 25];       // [h][c*5+cp]
__device__ __align__(256) float g_qk[HEADS * N * N];    // [h][i][j] raw q.k

// ---------------------------------------------------------------------------
// K1: qkv = w_qkv (384x128) @ x (128x512), TM=32,TN=64,TK=16, 256 threads,
// register-prefetch double buffering. Epilogue computes A2/B3/W4.
// ---------------------------------------------------------------------------
__global__ __launch_bounds__(256) void k_qkv(const float* __restrict__ A,
                                             const float* __restrict__ B,
                                             const float* __restrict__ w_ind,
                                             float* __restrict__ C) {
    __shared__ float As[16][32];
    __shared__ float Bs[16][64];
    __shared__ float Cs[32][65];
    __shared__ float wsm[32][5];
    const int n0 = blockIdx.x * 64;
    const int m0 = blockIdx.y * 32;
    const int t  = threadIdx.x;
    const int tx = t & 15, ty = t >> 4;

    // fixed per-thread load slots
    const int a_k = t & 15,  a_m = t >> 4;       // As: slots (a_k, a_m) and (a_k, a_m+16)
    const int b_n = t & 63,  b_k = t >> 6;       // Bs: slots (b_k+4r, b_n)

    // initial tile load (k0 = 0)
    As[a_k][a_m]      = A[(m0 + a_m) * DIM + a_k];
    As[a_k][a_m + 16] = A[(m0 + a_m + 16) * DIM + a_k];
#pragma unroll
    for (int r = 0; r < 4; r++)
        Bs[b_k + 4 * r][b_n] = B[(b_k + 4 * r) * N + n0 + b_n];
    __syncthreads();

    float acc[2][4] = {};
    for (int k0 = 0; k0 < DIM; k0 += 16) {
        float ra0 = 0.f, ra1 = 0.f, rb[4];
        const bool more = (k0 + 16 < DIM);
        if (more) {
            ra0 = A[(m0 + a_m) * DIM + k0 + 16 + a_k];
            ra1 = A[(m0 + a_m + 16) * DIM + k0 + 16 + a_k];
#pragma unroll
            for (int r = 0; r < 4; r++)
                rb[r] = B[(k0 + 16 + b_k + 4 * r) * N + n0 + b_n];
        }
#pragma unroll
        for (int kk = 0; kk < 16; kk++) {
            float2 a = ((const float2*)&As[kk][0])[ty];
            float4 b = ((const float4*)&Bs[kk][0])[tx];
            acc[0][0] = fmaf(a.x, b.x, acc[0][0]);
            acc[0][1] = fmaf(a.x, b.y, acc[0][1]);
            acc[0][2] = fmaf(a.x, b.z, acc[0][2]);
            acc[0][3] = fmaf(a.x, b.w, acc[0][3]);
            acc[1][0] = fmaf(a.y, b.x, acc[1][0]);
            acc[1][1] = fmaf(a.y, b.y, acc[1][1]);
            acc[1][2] = fmaf(a.y, b.z, acc[1][2]);
            acc[1][3] = fmaf(a.y, b.w, acc[1][3]);
        }
        __syncthreads();
        if (more) {
            As[a_k][a_m]      = ra0;
            As[a_k][a_m + 16] = ra1;
#pragma unroll
            for (int r = 0; r < 4; r++)
                Bs[b_k + 4 * r][b_n] = rb[r];
            __syncthreads();
        }
    }
    // write C and stage tile in smem
#pragma unroll
    for (int r = 0; r < 2; r++) {
        int m = ty * 2 + r;
        float* cp = &C[(m0 + m) * N + n0 + tx * 4];
        cp[0] = acc[r][0]; cp[1] = acc[r][1]; cp[2] = acc[r][2]; cp[3] = acc[r][3];
        Cs[m][tx * 4 + 0] = acc[r][0];
        Cs[m][tx * 4 + 1] = acc[r][1];
        Cs[m][tx * 4 + 2] = acc[r][2];
        Cs[m][tx * 4 + 3] = acc[r][3];
    }

    if (m0 < 2 * HID) {
        // A2 (q-blocks) / B3 (k-blocks): 64 cols x 5 coeffs, 32-deep dots
        const bool isQ = (m0 < HID);
        const int wbase = isQ ? (HID + m0) : (m0 - HID);   // wk rows for A2, wq rows for B3
        if (t < 160) wsm[t / 5][t % 5] = w_ind[(wbase + t / 5) * IND + (t % 5)];
        __syncthreads();
        const int h = (isQ ? m0 : m0 - HID) >> 5;
        float* dst = (isQ ? g_A2 : g_B3);
#pragma unroll
        for (int task = t; task < 320; task += 256) {
            int col = task & 63, c = task >> 6;
            float s = 0.f;
#pragma unroll
            for (int d = 0; d < DH; d++)
                s = fmaf(Cs[d][col], wsm[d][c], s);
            dst[(h * IND + c) * N + n0 + col] = s;
        }
    } else if (m0 == 2 * HID && n0 == 0) {
        if (t < HEADS * 25) {
            int h = t / 25, c = (t % 25) / 5, cp = t % 5;
            float s = 0.f;
#pragma unroll
            for (int d = 0; d < DH; d++)
                s = fmaf(w_ind[(h * DH + d) * IND + c],
                         w_ind[(HID + h * DH + d) * IND + cp], s);
            g_W4[t] = s;
        }
    }
}

// ---------------------------------------------------------------------------
// K2: g_qk[h][i][j] = sum_d q[h,d,i]*k[h,d,j].  64x64 tile, 4x4 rtile.
// ---------------------------------------------------------------------------
__global__ __launch_bounds__(256) void k_qk() {
    __shared__ float qs[DH][64];
    __shared__ float ks[DH][64];
    const int j0 = blockIdx.x * 64;
    const int i0 = blockIdx.y * 64;
    const int h  = blockIdx.z;
    const int t  = threadIdx.x;
    const int tx = t & 15, ty = t >> 4;

    const float* qb = g_qkv + (h * DH) * N;
    const float* kb = g_qkv + (HID + h * DH) * N;
#pragma unroll
    for (int idx = t; idx < DH * 16; idx += 256) {     // 512 float4 slots
        int d = idx >> 4, c4 = idx & 15;
        ((float4*)&qs[d][0])[c4] = ((const float4*)(qb + d * N + i0))[c4];
        ((float4*)&ks[d][0])[c4] = ((const float4*)(kb + d * N + j0))[c4];
    }
    __syncthreads();

    float acc[4][4] = {};
#pragma unroll
    for (int d = 0; d < DH; d++) {
        float4 qa = ((const float4*)&qs[d][0])[ty];
        float4 kv = ((const float4*)&ks[d][0])[tx];
        acc[0][0] = fmaf(qa.x, kv.x, acc[0][0]);
        acc[0][1] = fmaf(qa.x, kv.y, acc[0][1]);
        acc[0][2] = fmaf(qa.x, kv.z, acc[0][2]);
        acc[0][3] = fmaf(qa.x, kv.w, acc[0][3]);
        acc[1][0] = fmaf(qa.y, kv.x, acc[1][0]);
        acc[1][1] = fmaf(qa.y, kv.y, acc[1][1]);
        acc[1][2] = fmaf(qa.y, kv.z, acc[1][2]);
        acc[1][3] = fmaf(qa.y, kv.w, acc[1][3]);
        acc[2][0] = fmaf(qa.z, kv.x, acc[2][0]);
        acc[2][1] = fmaf(qa.z, kv.y, acc[2][1]);
        acc[2][2] = fmaf(qa.z, kv.z, acc[2][2]);
        acc[2][3] = fmaf(qa.z, kv.w, acc[2][3]);
        acc[3][0] = fmaf(qa.w, kv.x, acc[3][0]);
        acc[3][1] = fmaf(qa.w, kv.y, acc[3][1]);
        acc[3][2] = fmaf(qa.w, kv.z, acc[3][2]);
        acc[3][3] = fmaf(qa.w, kv.w, acc[3][3]);
    }
    float* cb = g_qk + ((size_t)h * N) * N;
#pragma unroll
    for (int r = 0; r < 4; r++) {
        int i = i0 + ty * 4 + r;
        ((float4*)&cb[(size_t)i * N + j0])[tx] =
            make_float4(acc[r][0], acc[r][1], acc[r][2], acc[r][3]);
    }
}

// ---------------------------------------------------------------------------
// K3: fused sim + softmax + attn@v + w_out projection.  TWO i's per block
// (grid 256, 256 threads); B3 loads and v streaming shared across the pair.
// ---------------------------------------------------------------------------
__global__ __launch_bounds__(256) void k_fused(const float* __restrict__ indicator,
                                               const float* __restrict__ w_out,
                                               const float* __restrict__ b_out,
                                               float* __restrict__ out) {
    const int i0 = blockIdx.x * 2;      // handles i0, i0+1
    const int t = threadIdx.x;          // owns j = 2t, 2t+1
    const int warp = t >> 5, lane = t & 31;

    __shared__ float a2s[2][HEADS][IND];
    __shared__ float w4s[HEADS][25];
    __shared__ float red[2][HEADS][8];
    __shared__ __align__(16) float ps[2][HEADS][N];   // probs (16 KB)
    __shared__ __align__(16) float avs[2][HID];

    if (t < 2 * HEADS * IND) {
        int ii = t / (HEADS * IND), u = t % (HEADS * IND);
        a2s[ii][u / IND][u % IND] = g_A2[u * N + i0 + ii];
    } else if (t < 2 * HEADS * IND + HEADS * 25) {
        int u = t - 2 * HEADS * IND;
        w4s[u / 25][u % 25] = g_W4[u];
    }
    __syncthreads();

    // ---- indicator loads for both i ----
    float2 iv[2][IND];
#pragma unroll
    for (int ii = 0; ii < 2; ii++)
#pragma unroll
        for (int c = 0; c < IND; c++)
            iv[ii][c] = *(const float2*)(indicator + ((size_t)c * N + i0 + ii) * N + 2 * t);

    // ---- sim: B3 loaded once per (h,c), shared across the i-pair ----
    float2 sim[2][HEADS];
#pragma unroll
    for (int h = 0; h < HEADS; h++) {
        float2 b3[IND];
#pragma unroll
        for (int c = 0; c < IND; c++)
            b3[c] = *(const float2*)(g_B3 + (h * IND + c) * N + 2 * t);
#pragma unroll
        for (int ii = 0; ii < 2; ii++) {
            float2 qk = *(const float2*)(g_qk + ((size_t)h * N + i0 + ii) * N + 2 * t);
            float linx = 0.f, liny = 0.f, quadx = 0.f, quady = 0.f;
#pragma unroll
            for (int c = 0; c < IND; c++) {
                float a2 = a2s[ii][h][c];
                linx = fmaf(iv[ii][c].x, a2 + b3[c].x, linx);
                liny = fmaf(iv[ii][c].y, a2 + b3[c].y, liny);
                float tx2 = 0.f, ty2 = 0.f;
#pragma unroll
                for (int cp = 0; cp < IND; cp++) {
                    float w = w4s[h][c * 5 + cp];
                    tx2 = fmaf(w, iv[ii][cp].x, tx2);
                    ty2 = fmaf(w, iv[ii][cp].y, ty2);
                }
                quadx = fmaf(iv[ii][c].x, tx2, quadx);
                quady = fmaf(iv[ii][c].y, ty2, quady);
            }
            sim[ii][h].x = ATTN_SCALE * (qk.x + linx + quadx);
            sim[ii][h].y = ATTN_SCALE * (qk.y + liny + quady);
        }
    }

    // ---- softmax: max reduce (8 lanes of reduction data) ----
    float m4[2][HEADS];
#pragma unroll
    for (int ii = 0; ii < 2; ii++)
#pragma unroll
        for (int h = 0; h < HEADS; h++)
            m4[ii][h] = fmaxf(sim[ii][h].x, sim[ii][h].y);
#pragma unroll
    for (int off = 16; off; off >>= 1)
#pragma unroll
        for (int ii = 0; ii < 2; ii++)
#pragma unroll
            for (int h = 0; h < HEADS; h++)
                m4[ii][h] = fmaxf(m4[ii][h], __shfl_xor_sync(0xffffffffu, m4[ii][h], off));
    if (lane == 0)
#pragma unroll
        for (int ii = 0; ii < 2; ii++)
#pragma unroll
            for (int h = 0; h < HEADS; h++) red[ii][h][warp] = m4[ii][h];
    __syncthreads();
    float gmax[2][HEADS];
#pragma unroll
    for (int ii = 0; ii < 2; ii++)
#pragma unroll
        for (int h = 0; h < HEADS; h++) {
            float g = red[ii][h][0];
#pragma unroll
            for (int w = 1; w < 8; w++) g = fmaxf(g, red[ii][h][w]);
            gmax[ii][h] = g;
        }
    __syncthreads();

    // ---- exp + sum reduce ----
    float2 e[2][HEADS];
    float ss[2][HEADS];
#pragma unroll
    for (int ii = 0; ii < 2; ii++)
#pragma unroll
        for (int h = 0; h < HEADS; h++) {
            e[ii][h].x = __expf(sim[ii][h].x - gmax[ii][h]);
            e[ii][h].y = __expf(sim[ii][h].y - gmax[ii][h]);
            ss[ii][h] = e[ii][h].x + e[ii][h].y;
        }
#pragma unroll
    for (int off = 16; off; off >>= 1)
#pragma unroll
        for (int ii = 0; ii < 2; ii++)
#pragma unroll
            for (int h = 0; h < HEADS; h++)
                ss[ii][h] += __shfl_xor_sync(0xffffffffu, ss[ii][h], off);
    if (lane == 0)
#pragma unroll
        for (int ii = 0; ii < 2; ii++)
#pragma unroll
            for (int h = 0; h < HEADS; h++) red[ii][h][warp] = ss[ii][h];
    __syncthreads();
#pragma unroll
    for (int ii = 0; ii < 2; ii++)
#pragma unroll
        for (int h = 0; h < HEADS; h++) {
            float g = 0.f;
#pragma unroll
            for (int w = 0; w < 8; w++) g += red[ii][h][w];
            float inv = 1.0f / g;
            float2 p;
            p.x = e[ii][h].x * inv; p.y = e[ii][h].y * inv;
            *(float2*)&ps[ii][h][2 * t] = p;
        }
    __syncthreads();

    // ---- attn@v: v loaded once, used for both i ----
#pragma unroll
    for (int rr = 0; rr < 16; rr++) {
        int row = warp * 16 + rr;            // 0..127
        int h = row >> 5;
        const float4* vr = (const float4*)(g_qkv + (2 * HID + row) * N);
        const float4* p0 = (const float4*)&ps[0][h][0];
        const float4* p1 = (const float4*)&ps[1][h][0];
        float acc0 = 0.f, acc1 = 0.f;
#pragma unroll
        for (int u = lane; u < N / 4; u += 32) {
            float4 v4 = vr[u];
            float4 a4 = p0[u];
            float4 b4 = p1[u];
            acc0 = fmaf(v4.x, a4.x, acc0);
            acc0 = fmaf(v4.y, a4.y, acc0);
            acc0 = fmaf(v4.z, a4.z, acc0);
            acc0 = fmaf(v4.w, a4.w, acc0);
            acc1 = fmaf(v4.x, b4.x, acc1);
            acc1 = fmaf(v4.y, b4.y, acc1);
            acc1 = fmaf(v4.z, b4.z, acc1);
            acc1 = fmaf(v4.w, b4.w, acc1);
        }
#pragma unroll
        for (int off = 16; off; off >>= 1) {
            acc0 += __shfl_xor_sync(0xffffffffu, acc0, off);
            acc1 += __shfl_xor_sync(0xffffffffu, acc1, off);
        }
        if (lane == 0) { avs[0][row] = acc0; avs[1][row] = acc1; }
    }
    __syncthreads();

    // ---- projection for both i ----
#pragma unroll
    for (int rr = 0; rr < 16; rr++) {
        int o = warp * 16 + rr;              // 0..127
        float4 w4 = ((const float4*)(w_out + o * HID))[lane];
        float4 a0 = ((const float4*)&avs[0][0])[lane];
        float4 a1 = ((const float4*)&avs[1][0])[lane];
        float acc0 = w4.x * a0.x + w4.y * a0.y + w4.z * a0.z + w4.w * a0.w;
        float acc1 = w4.x * a1.x + w4.y * a1.y + w4.z * a1.z + w4.w * a1.w;
#pragma unroll
        for (int off = 16; off; off >>= 1) {
            acc0 += __shfl_xor_sync(0xffffffffu, acc0, off);
            acc1 += __shfl_xor_sync(0xffffffffu, acc1, off);
        }
        if (lane == 0) {
            float bv = b_out[o];
            out[o * N + i0]     = acc0 + bv;
            out[o * N + i0 + 1] = acc1 + bv;
        }
    }
}

// ---------------------------------------------------------------------------
extern "C" void kernel_launch(void* const* d_in, const int* in_sizes, int n_in,
                              void* d_out, int out_size) {
    const float* x         = (const float*)d_in[0];   // (1,128,512)
    const float* indicator = (const float*)d_in[1];   // (1,5,512,512)
    const float* w_qkv     = (const float*)d_in[2];   // (384,128)
    const float* w_ind     = (const float*)d_in[3];   // (256,5)
    const float* w_out     = (const float*)d_in[4];   // (128,128)
    const float* b_out     = (const float*)d_in[5];   // (128,)
    float* out             = (float*)d_out;           // (1,128,512)

    float* qkv;  cudaGetSymbolAddress((void**)&qkv, g_qkv);

    k_qkv<<<dim3(8, 12), 256>>>(w_qkv, x, w_ind, qkv);    // qkv + A2/B3/W4
    k_qk<<<dim3(8, 8, 4), 256>>>();                        // raw q.k
    k_fused<<<N / 2, 256>>>(indicator, w_out, b_out, out); // sim+softmax+av+proj
}

// round 10
// speedup vs baseline: 1.5230x; 1.0225x over previous
#include <cuda_runtime.h>

#define DIM 128
#define N 512
#define HEADS 4
#define DH 32
#define HID 128
#define IND 5
#define ATTN_SCALE 0.17677669529663687f   // 32^-0.5

// Scratch (allocation-free rule: __device__ globals). 256B-aligned (vector access).
__device__ __align__(256) float g_qkv[3 * HID * N];     // [384][512] q|k|v
__device__ __align__(256) float g_A2[HEADS * IND * N];  // [h][c][i]
__device__ __align__(256) float g_B3[HEADS * IND * N];  // [h][c][j]
__device__ __align__(256) float g_W4[HEADS * 25];       // [h][c*5+cp]
__device__ __align__(256) float g_qk[HEADS * N * N];    // [h][i][j] raw q.k

// ---------------------------------------------------------------------------
// K1: qkv = w_qkv (384x128) @ x (128x512). TM=32, TN=32, TK=16, 256 threads,
// grid (16,12)=192 blocks (>=148 SMs to dodge the low-grid issue throttle).
// Register double-buffer; epilogue computes A2/B3 (per-head blocks) and W4.
// ---------------------------------------------------------------------------
__global__ __launch_bounds__(256) void k_qkv(const float* __restrict__ A,
                                             const float* __restrict__ B,
                                             const float* __restrict__ w_ind,
                                             float* __restrict__ C) {
    __shared__ float As[16][32];
    __shared__ float Bs[16][32];
    __shared__ float Cs[32][33];
    __shared__ float wsm[32][5];
    const int n0 = blockIdx.x * 32;
    const int m0 = blockIdx.y * 32;
    const int t  = threadIdx.x;
    const int tx = t & 15, ty = t >> 4;

    // fixed per-thread load slots
    const int a_k = t & 15, a_m = t >> 4;    // As: (a_k, a_m), (a_k, a_m+16)
    const int b_n = t & 31, b_k = t >> 5;    // Bs: (b_k, b_n), (b_k+8, b_n)

    // initial tile (k0 = 0)
    As[a_k][a_m]      = A[(m0 + a_m) * DIM + a_k];
    As[a_k][a_m + 16] = A[(m0 + a_m + 16) * DIM + a_k];
    Bs[b_k][b_n]      = B[b_k * N + n0 + b_n];
    Bs[b_k + 8][b_n]  = B[(b_k + 8) * N + n0 + b_n];
    __syncthreads();

    float acc[2][2] = {};
    for (int k0 = 0; k0 < DIM; k0 += 16) {
        float ra0 = 0.f, ra1 = 0.f, rb0 = 0.f, rb1 = 0.f;
        const bool more = (k0 + 16 < DIM);
        if (more) {
            ra0 = A[(m0 + a_m) * DIM + k0 + 16 + a_k];
            ra1 = A[(m0 + a_m + 16) * DIM + k0 + 16 + a_k];
            rb0 = B[(k0 + 16 + b_k) * N + n0 + b_n];
            rb1 = B[(k0 + 24 + b_k) * N + n0 + b_n];
        }
#pragma unroll
        for (int kk = 0; kk < 16; kk++) {
            float2 a = ((const float2*)&As[kk][0])[ty];
            float2 b = ((const float2*)&Bs[kk][0])[tx];
            acc[0][0] = fmaf(a.x, b.x, acc[0][0]);
            acc[0][1] = fmaf(a.x, b.y, acc[0][1]);
            acc[1][0] = fmaf(a.y, b.x, acc[1][0]);
            acc[1][1] = fmaf(a.y, b.y, acc[1][1]);
        }
        __syncthreads();
        if (more) {
            As[a_k][a_m]      = ra0;
            As[a_k][a_m + 16] = ra1;
            Bs[b_k][b_n]      = rb0;
            Bs[b_k + 8][b_n]  = rb1;
            __syncthreads();
        }
    }
    // write C and stage tile in smem
#pragma unroll
    for (int r = 0; r < 2; r++) {
        int m = ty * 2 + r;
        float* cp = &C[(m0 + m) * N + n0 + tx * 2];
        cp[0] = acc[r][0]; cp[1] = acc[r][1];
        Cs[m][tx * 2 + 0] = acc[r][0];
        Cs[m][tx * 2 + 1] = acc[r][1];
    }

    if (m0 < 2 * HID) {
        // A2 (q-blocks) / B3 (k-blocks): 32 cols x 5 coeffs, 32-deep dots
        const bool isQ = (m0 < HID);
        const int wbase = isQ ? (HID + m0) : (m0 - HID);   // wk rows for A2, wq rows for B3
        if (t < 160) wsm[t / 5][t % 5] = w_ind[(wbase + t / 5) * IND + (t % 5)];
        __syncthreads();
        const int h = (isQ ? m0 : m0 - HID) >> 5;
        float* dst = (isQ ? g_A2 : g_B3);
        if (t < 160) {
            int col = t & 31, c = t >> 5;
            float s = 0.f;
#pragma unroll
            for (int d = 0; d < DH; d++)
                s = fmaf(Cs[d][col], wsm[d][c], s);
            dst[(h * IND + c) * N + n0 + col] = s;
        }
    } else if (m0 == 2 * HID && n0 == 0) {
        if (t < HEADS * 25) {
            int h = t / 25, c = (t % 25) / 5, cp = t % 5;
            float s = 0.f;
#pragma unroll
            for (int d = 0; d < DH; d++)
                s = fmaf(w_ind[(h * DH + d) * IND + c],
                         w_ind[(HID + h * DH + d) * IND + cp], s);
            g_W4[t] = s;
        }
    }
}

// ---------------------------------------------------------------------------
// K2: g_qk[h][i][j] = sum_d q[h,d,i]*k[h,d,j].  64x64 tile, 4x4 rtile.
// ---------------------------------------------------------------------------
__global__ __launch_bounds__(256) void k_qk() {
    __shared__ float qs[DH][64];
    __shared__ float ks[DH][64];
    const int j0 = blockIdx.x * 64;
    const int i0 = blockIdx.y * 64;
    const int h  = blockIdx.z;
    const int t  = threadIdx.x;
    const int tx = t & 15, ty = t >> 4;

    const float* qb = g_qkv + (h * DH) * N;
    const float* kb = g_qkv + (HID + h * DH) * N;
#pragma unroll
    for (int idx = t; idx < DH * 16; idx += 256) {     // 512 float4 slots
        int d = idx >> 4, c4 = idx & 15;
        ((float4*)&qs[d][0])[c4] = ((const float4*)(qb + d * N + i0))[c4];
        ((float4*)&ks[d][0])[c4] = ((const float4*)(kb + d * N + j0))[c4];
    }
    __syncthreads();

    float acc[4][4] = {};
#pragma unroll
    for (int d = 0; d < DH; d++) {
        float4 qa = ((const float4*)&qs[d][0])[ty];
        float4 kv = ((const float4*)&ks[d][0])[tx];
        acc[0][0] = fmaf(qa.x, kv.x, acc[0][0]);
        acc[0][1] = fmaf(qa.x, kv.y, acc[0][1]);
        acc[0][2] = fmaf(qa.x, kv.z, acc[0][2]);
        acc[0][3] = fmaf(qa.x, kv.w, acc[0][3]);
        acc[1][0] = fmaf(qa.y, kv.x, acc[1][0]);
        acc[1][1] = fmaf(qa.y, kv.y, acc[1][1]);
        acc[1][2] = fmaf(qa.y, kv.z, acc[1][2]);
        acc[1][3] = fmaf(qa.y, kv.w, acc[1][3]);
        acc[2][0] = fmaf(qa.z, kv.x, acc[2][0]);
        acc[2][1] = fmaf(qa.z, kv.y, acc[2][1]);
        acc[2][2] = fmaf(qa.z, kv.z, acc[2][2]);
        acc[2][3] = fmaf(qa.z, kv.w, acc[2][3]);
        acc[3][0] = fmaf(qa.w, kv.x, acc[3][0]);
        acc[3][1] = fmaf(qa.w, kv.y, acc[3][1]);
        acc[3][2] = fmaf(qa.w, kv.z, acc[3][2]);
        acc[3][3] = fmaf(qa.w, kv.w, acc[3][3]);
    }
    float* cb = g_qk + ((size_t)h * N) * N;
#pragma unroll
    for (int r = 0; r < 4; r++) {
        int i = i0 + ty * 4 + r;
        ((float4*)&cb[(size_t)i * N + j0])[tx] =
            make_float4(acc[r][0], acc[r][1], acc[r][2], acc[r][3]);
    }
}

// ---------------------------------------------------------------------------
// K3: fused sim + softmax + attn@v + w_out projection.  TWO i's per block
// (grid 256, 256 threads); B3 loads and v streaming shared across the pair.
// ---------------------------------------------------------------------------
__global__ __launch_bounds__(256) void k_fused(const float* __restrict__ indicator,
                                               const float* __restrict__ w_out,
                                               const float* __restrict__ b_out,
                                               float* __restrict__ out) {
    const int i0 = blockIdx.x * 2;      // handles i0, i0+1
    const int t = threadIdx.x;          // owns j = 2t, 2t+1
    const int warp = t >> 5, lane = t & 31;

    __shared__ float a2s[2][HEADS][IND];
    __shared__ float w4s[HEADS][25];
    __shared__ float red[2][HEADS][8];
    __shared__ __align__(16) float ps[2][HEADS][N];   // probs (16 KB)
    __shared__ __align__(16) float avs[2][HID];

    if (t < 2 * HEADS * IND) {
        int ii = t / (HEADS * IND), u = t % (HEADS * IND);
        a2s[ii][u / IND][u % IND] = g_A2[u * N + i0 + ii];
    } else if (t < 2 * HEADS * IND + HEADS * 25) {
        int u = t - 2 * HEADS * IND;
        w4s[u / 25][u % 25] = g_W4[u];
    }
    __syncthreads();

    // ---- indicator loads for both i ----
    float2 iv[2][IND];
#pragma unroll
    for (int ii = 0; ii < 2; ii++)
#pragma unroll
        for (int c = 0; c < IND; c++)
            iv[ii][c] = *(const float2*)(indicator + ((size_t)c * N + i0 + ii) * N + 2 * t);

    // ---- sim: B3 loaded once per (h,c), shared across the i-pair ----
    float2 sim[2][HEADS];
#pragma unroll
    for (int h = 0; h < HEADS; h++) {
        float2 b3[IND];
#pragma unroll
        for (int c = 0; c < IND; c++)
            b3[c] = *(const float2*)(g_B3 + (h * IND + c) * N + 2 * t);
#pragma unroll
        for (int ii = 0; ii < 2; ii++) {
            float2 qk = *(const float2*)(g_qk + ((size_t)h * N + i0 + ii) * N + 2 * t);
            float linx = 0.f, liny = 0.f, quadx = 0.f, quady = 0.f;
#pragma unroll
            for (int c = 0; c < IND; c++) {
                float a2 = a2s[ii][h][c];
                linx = fmaf(iv[ii][c].x, a2 + b3[c].x, linx);
                liny = fmaf(iv[ii][c].y, a2 + b3[c].y, liny);
                float tx2 = 0.f, ty2 = 0.f;
#pragma unroll
                for (int cp = 0; cp < IND; cp++) {
                    float w = w4s[h][c * 5 + cp];
                    tx2 = fmaf(w, iv[ii][cp].x, tx2);
                    ty2 = fmaf(w, iv[ii][cp].y, ty2);
                }
                quadx = fmaf(iv[ii][c].x, tx2, quadx);
                quady = fmaf(iv[ii][c].y, ty2, quady);
            }
            sim[ii][h].x = ATTN_SCALE * (qk.x + linx + quadx);
            sim[ii][h].y = ATTN_SCALE * (qk.y + liny + quady);
        }
    }

    // ---- softmax: max reduce ----
    float m4[2][HEADS];
#pragma unroll
    for (int ii = 0; ii < 2; ii++)
#pragma unroll
        for (int h = 0; h < HEADS; h++)
            m4[ii][h] = fmaxf(sim[ii][h].x, sim[ii][h].y);
#pragma unroll
    for (int off = 16; off; off >>= 1)
#pragma unroll
        for (int ii = 0; ii < 2; ii++)
#pragma unroll
            for (int h = 0; h < HEADS; h++)
                m4[ii][h] = fmaxf(m4[ii][h], __shfl_xor_sync(0xffffffffu, m4[ii][h], off));
    if (lane == 0)
#pragma unroll
        for (int ii = 0; ii < 2; ii++)
#pragma unroll
            for (int h = 0; h < HEADS; h++) red[ii][h][warp] = m4[ii][h];
    __syncthreads();
    float gmax[2][HEADS];
#pragma unroll
    for (int ii = 0; ii < 2; ii++)
#pragma unroll
        for (int h = 0; h < HEADS; h++) {
            float g = red[ii][h][0];
#pragma unroll
            for (int w = 1; w < 8; w++) g = fmaxf(g, red[ii][h][w]);
            gmax[ii][h] = g;
        }
    __syncthreads();

    // ---- exp + sum reduce ----
    float2 e[2][HEADS];
    float ss[2][HEADS];
#pragma unroll
    for (int ii = 0; ii < 2; ii++)
#pragma unroll
        for (int h = 0; h < HEADS; h++) {
            e[ii][h].x = __expf(sim[ii][h].x - gmax[ii][h]);
            e[ii][h].y = __expf(sim[ii][h].y - gmax[ii][h]);
            ss[ii][h] = e[ii][h].x + e[ii][h].y;
        }
#pragma unroll
    for (int off = 16; off; off >>= 1)
#pragma unroll
        for (int ii = 0; ii < 2; ii++)
#pragma unroll
            for (int h = 0; h < HEADS; h++)
                ss[ii][h] += __shfl_xor_sync(0xffffffffu, ss[ii][h], off);
    if (lane == 0)
#pragma unroll
        for (int ii = 0; ii < 2; ii++)
#pragma unroll
            for (int h = 0; h < HEADS; h++) red[ii][h][warp] = ss[ii][h];
    __syncthreads();
#pragma unroll
    for (int ii = 0; ii < 2; ii++)
#pragma unroll
        for (int h = 0; h < HEADS; h++) {
            float g = 0.f;
#pragma unroll
            for (int w = 0; w < 8; w++) g += red[ii][h][w];
            float inv = 1.0f / g;
            float2 p;
            p.x = e[ii][h].x * inv; p.y = e[ii][h].y * inv;
            *(float2*)&ps[ii][h][2 * t] = p;
        }
    __syncthreads();

    // ---- attn@v: v loaded once, used for both i ----
#pragma unroll
    for (int rr = 0; rr < 16; rr++) {
        int row = warp * 16 + rr;            // 0..127
        int h = row >> 5;
        const float4* vr = (const float4*)(g_qkv + (2 * HID + row) * N);
        const float4* p0 = (const float4*)&ps[0][h][0];
        const float4* p1 = (const float4*)&ps[1][h][0];
        float acc0 = 0.f, acc1 = 0.f;
#pragma unroll
        for (int u = lane; u < N / 4; u += 32) {
            float4 v4 = vr[u];
            float4 a4 = p0[u];
            float4 b4 = p1[u];
            acc0 = fmaf(v4.x, a4.x, acc0);
            acc0 = fmaf(v4.y, a4.y, acc0);
            acc0 = fmaf(v4.z, a4.z, acc0);
            acc0 = fmaf(v4.w, a4.w, acc0);
            acc1 = fmaf(v4.x, b4.x, acc1);
            acc1 = fmaf(v4.y, b4.y, acc1);
            acc1 = fmaf(v4.z, b4.z, acc1);
            acc1 = fmaf(v4.w, b4.w, acc1);
        }
#pragma unroll
        for (int off = 16; off; off >>= 1) {
            acc0 += __shfl_xor_sync(0xffffffffu, acc0, off);
            acc1 += __shfl_xor_sync(0xffffffffu, acc1, off);
        }
        if (lane == 0) { avs[0][row] = acc0; avs[1][row] = acc1; }
    }
    __syncthreads();

    // ---- projection for both i ----
#pragma unroll
    for (int rr = 0; rr < 16; rr++) {
        int o = warp * 16 + rr;              // 0..127
        float4 w4 = ((const float4*)(w_out + o * HID))[lane];
        float4 a0 = ((const float4*)&avs[0][0])[lane];
        float4 a1 = ((const float4*)&avs[1][0])[lane];
        float acc0 = w4.x * a0.x + w4.y * a0.y + w4.z * a0.z + w4.w * a0.w;
        float acc1 = w4.x * a1.x + w4.y * a1.y + w4.z * a1.z + w4.w * a1.w;
#pragma unroll
        for (int off = 16; off; off >>= 1) {
            acc0 += __shfl_xor_sync(0xffffffffu, acc0, off);
            acc1 += __shfl_xor_sync(0xffffffffu, acc1, off);
        }
        if (lane == 0) {
            float bv = b_out[o];
            out[o * N + i0]     = acc0 + bv;
            out[o * N + i0 + 1] = acc1 + bv;
        }
    }
}

// ---------------------------------------------------------------------------
extern "C" void kernel_launch(void* const* d_in, const int* in_sizes, int n_in,
                              void* d_out, int out_size) {
    const float* x         = (const float*)d_in[0];   // (1,128,512)
    const float* indicator = (const float*)d_in[1];   // (1,5,512,512)
    const float* w_qkv     = (const float*)d_in[2];   // (384,128)
    const float* w_ind     = (const float*)d_in[3];   // (256,5)
    const float* w_out     = (const float*)d_in[4];   // (128,128)
    const float* b_out     = (const float*)d_in[5];   // (128,)
    float* out             = (float*)d_out;           // (1,128,512)

    float* qkv;  cudaGetSymbolAddress((void**)&qkv, g_qkv);

    k_qkv<<<dim3(16, 12), 256>>>(w_qkv, x, w_ind, qkv);   // qkv + A2/B3/W4
    k_qk<<<dim3(8, 8, 4), 256>>>();                        // raw q.k
    k_fused<<<N / 2, 256>>>(indicator, w_out, b_out, out); // sim+softmax+av+proj
}

// round 11
// speedup vs baseline: 1.5246x; 1.0010x over previous
#include <cuda_runtime.h>

#define DIM 128
#define N 512
#define HEADS 4
#define DH 32
#define HID 128
#define IND 5
#define ATTN_SCALE 0.17677669529663687f   // 32^-0.5

// Scratch (allocation-free rule: __device__ globals). 256B-aligned (vector access).
__device__ __align__(256) float g_qkv[3 * HID * N];     // [384][512] q|k|v
__device__ __align__(256) float g_A2[HEADS * IND * N];  // [h][c][i]
__device__ __align__(256) float g_B3[HEADS * IND * N];  // [h][c][j]
__device__ __align__(256) float g_W4[HEADS * 25];       // [h][c*5+cp]
__device__ __align__(256) float g_qk[HEADS * N * N];    // [h][i][j] raw q.k

// ---------------------------------------------------------------------------
// K1: qkv = w_qkv (384x128) @ x (128x512). TM=32, TN=32, TK=16, 256 threads,
// grid (16,12)=192 blocks. Register double-buffer; epilogue computes A2/B3/W4.
// ---------------------------------------------------------------------------
__global__ __launch_bounds__(256) void k_qkv(const float* __restrict__ A,
                                             const float* __restrict__ B,
                                             const float* __restrict__ w_ind,
                                             float* __restrict__ C) {
    __shared__ float As[16][32];
    __shared__ float Bs[16][32];
    __shared__ float Cs[32][33];
    __shared__ float wsm[32][5];
    const int n0 = blockIdx.x * 32;
    const int m0 = blockIdx.y * 32;
    const int t  = threadIdx.x;
    const int tx = t & 15, ty = t >> 4;

    const int a_k = t & 15, a_m = t >> 4;
    const int b_n = t & 31, b_k = t >> 5;

    As[a_k][a_m]      = A[(m0 + a_m) * DIM + a_k];
    As[a_k][a_m + 16] = A[(m0 + a_m + 16) * DIM + a_k];
    Bs[b_k][b_n]      = B[b_k * N + n0 + b_n];
    Bs[b_k + 8][b_n]  = B[(b_k + 8) * N + n0 + b_n];
    __syncthreads();

    float acc[2][2] = {};
    for (int k0 = 0; k0 < DIM; k0 += 16) {
        float ra0 = 0.f, ra1 = 0.f, rb0 = 0.f, rb1 = 0.f;
        const bool more = (k0 + 16 < DIM);
        if (more) {
            ra0 = A[(m0 + a_m) * DIM + k0 + 16 + a_k];
            ra1 = A[(m0 + a_m + 16) * DIM + k0 + 16 + a_k];
            rb0 = B[(k0 + 16 + b_k) * N + n0 + b_n];
            rb1 = B[(k0 + 24 + b_k) * N + n0 + b_n];
        }
#pragma unroll
        for (int kk = 0; kk < 16; kk++) {
            float2 a = ((const float2*)&As[kk][0])[ty];
            float2 b = ((const float2*)&Bs[kk][0])[tx];
            acc[0][0] = fmaf(a.x, b.x, acc[0][0]);
            acc[0][1] = fmaf(a.x, b.y, acc[0][1]);
            acc[1][0] = fmaf(a.y, b.x, acc[1][0]);
            acc[1][1] = fmaf(a.y, b.y, acc[1][1]);
        }
        __syncthreads();
        if (more) {
            As[a_k][a_m]      = ra0;
            As[a_k][a_m + 16] = ra1;
            Bs[b_k][b_n]      = rb0;
            Bs[b_k + 8][b_n]  = rb1;
            __syncthreads();
        }
    }
#pragma unroll
    for (int r = 0; r < 2; r++) {
        int m = ty * 2 + r;
        float* cp = &C[(m0 + m) * N + n0 + tx * 2];
        cp[0] = acc[r][0]; cp[1] = acc[r][1];
        Cs[m][tx * 2 + 0] = acc[r][0];
        Cs[m][tx * 2 + 1] = acc[r][1];
    }

    if (m0 < 2 * HID) {
        const bool isQ = (m0 < HID);
        const int wbase = isQ ? (HID + m0) : (m0 - HID);
        if (t < 160) wsm[t / 5][t % 5] = w_ind[(wbase + t / 5) * IND + (t % 5)];
        __syncthreads();
        const int h = (isQ ? m0 : m0 - HID) >> 5;
        float* dst = (isQ ? g_A2 : g_B3);
        if (t < 160) {
            int col = t & 31, c = t >> 5;
            float s = 0.f;
#pragma unroll
            for (int d = 0; d < DH; d++)
                s = fmaf(Cs[d][col], wsm[d][c], s);
            dst[(h * IND + c) * N + n0 + col] = s;
        }
    } else if (m0 == 2 * HID && n0 == 0) {
        if (t < HEADS * 25) {
            int h = t / 25, c = (t % 25) / 5, cp = t % 5;
            float s = 0.f;
#pragma unroll
            for (int d = 0; d < DH; d++)
                s = fmaf(w_ind[(h * DH + d) * IND + c],
                         w_ind[(HID + h * DH + d) * IND + cp], s);
            g_W4[t] = s;
        }
    }
}

// ---------------------------------------------------------------------------
// K2: g_qk[h][i][j] = sum_d q[h,d,i]*k[h,d,j].  64x64 tile, 4x4 rtile.
// ---------------------------------------------------------------------------
__global__ __launch_bounds__(256) void k_qk() {
    __shared__ float qs[DH][64];
    __shared__ float ks[DH][64];
    const int j0 = blockIdx.x * 64;
    const int i0 = blockIdx.y * 64;
    const int h  = blockIdx.z;
    const int t  = threadIdx.x;
    const int tx = t & 15, ty = t >> 4;

    const float* qb = g_qkv + (h * DH) * N;
    const float* kb = g_qkv + (HID + h * DH) * N;
#pragma unroll
    for (int idx = t; idx < DH * 16; idx += 256) {
        int d = idx >> 4, c4 = idx & 15;
        ((float4*)&qs[d][0])[c4] = ((const float4*)(qb + d * N + i0))[c4];
        ((float4*)&ks[d][0])[c4] = ((const float4*)(kb + d * N + j0))[c4];
    }
    __syncthreads();

    float acc[4][4] = {};
#pragma unroll
    for (int d = 0; d < DH; d++) {
        float4 qa = ((const float4*)&qs[d][0])[ty];
        float4 kv = ((const float4*)&ks[d][0])[tx];
        acc[0][0] = fmaf(qa.x, kv.x, acc[0][0]);
        acc[0][1] = fmaf(qa.x, kv.y, acc[0][1]);
        acc[0][2] = fmaf(qa.x, kv.z, acc[0][2]);
        acc[0][3] = fmaf(qa.x, kv.w, acc[0][3]);
        acc[1][0] = fmaf(qa.y, kv.x, acc[1][0]);
        acc[1][1] = fmaf(qa.y, kv.y, acc[1][1]);
        acc[1][2] = fmaf(qa.y, kv.z, acc[1][2]);
        acc[1][3] = fmaf(qa.y, kv.w, acc[1][3]);
        acc[2][0] = fmaf(qa.z, kv.x, acc[2][0]);
        acc[2][1] = fmaf(qa.z, kv.y, acc[2][1]);
        acc[2][2] = fmaf(qa.z, kv.z, acc[2][2]);
        acc[2][3] = fmaf(qa.z, kv.w, acc[2][3]);
        acc[3][0] = fmaf(qa.w, kv.x, acc[3][0]);
        acc[3][1] = fmaf(qa.w, kv.y, acc[3][1]);
        acc[3][2] = fmaf(qa.w, kv.z, acc[3][2]);
        acc[3][3] = fmaf(qa.w, kv.w, acc[3][3]);
    }
    float* cb = g_qk + ((size_t)h * N) * N;
#pragma unroll
    for (int r = 0; r < 4; r++) {
        int i = i0 + ty * 4 + r;
        ((float4*)&cb[(size_t)i * N + j0])[tx] =
            make_float4(acc[r][0], acc[r][1], acc[r][2], acc[r][3]);
    }
}

// ---------------------------------------------------------------------------
// K3: fused sim + softmax + attn@v + w_out projection.  FOUR i's per block,
// 512 threads (grid 128). Raw sims staged in smem; softmax as a
// warp-per-(i,h) smem pass (no big register arrays). v streamed once per 4 i.
// ---------------------------------------------------------------------------
__global__ __launch_bounds__(512) void k_fused(const float* __restrict__ indicator,
                                               const float* __restrict__ w_out,
                                               const float* __restrict__ b_out,
                                               float* __restrict__ out) {
    const int i0 = blockIdx.x * 4;      // handles i0..i0+3
    const int t = threadIdx.x;          // Pass A: owns column j = t
    const int warp = t >> 5, lane = t & 31;

    __shared__ float a2s[4][HEADS][IND];
    __shared__ float w4s[HEADS][25];
    __shared__ float inv_s[4][HEADS];
    __shared__ __align__(16) float ps[4][HEADS][N];   // 32 KB: sims -> probs
    __shared__ __align__(16) float avs[4][HID];       // 2 KB

    if (t < 80) {
        int ii = t / 20, u = t % 20;
        a2s[ii][u / 5][u % 5] = g_A2[u * N + i0 + ii];
    } else if (t < 180) {
        int u = t - 80;
        w4s[u / 25][u % 25] = g_W4[u];
    }
    __syncthreads();

    // ---- Pass A: raw sims into smem ----
#pragma unroll
    for (int ii = 0; ii < 4; ii++) {
        float iv[IND];
#pragma unroll
        for (int c = 0; c < IND; c++)
            iv[c] = indicator[((size_t)c * N + i0 + ii) * N + t];
#pragma unroll
        for (int h = 0; h < HEADS; h++) {
            float qk = g_qk[((size_t)h * N + i0 + ii) * N + t];
            float lin = 0.f, quad = 0.f;
#pragma unroll
            for (int c = 0; c < IND; c++) {
                float b3 = g_B3[(h * IND + c) * N + t];
                lin = fmaf(iv[c], a2s[ii][h][c] + b3, lin);
                float tt = 0.f;
#pragma unroll
                for (int cp = 0; cp < IND; cp++)
                    tt = fmaf(w4s[h][c * 5 + cp], iv[cp], tt);
                quad = fmaf(iv[c], tt, quad);
            }
            ps[ii][h][t] = ATTN_SCALE * (qk + lin + quad);
        }
    }
    __syncthreads();

    // ---- softmax: one warp per (ii,h) pair over its 512 sims ----
    {
        const int ii = warp >> 2, h = warp & 3;
        float4* pr = (float4*)&ps[ii][h][0];
        float4 vals[4];
        float m = -1e30f;
#pragma unroll
        for (int k2 = 0; k2 < 4; k2++) {
            vals[k2] = pr[lane + 32 * k2];
            m = fmaxf(m, fmaxf(fmaxf(vals[k2].x, vals[k2].y),
                               fmaxf(vals[k2].z, vals[k2].w)));
        }
#pragma unroll
        for (int off = 16; off; off >>= 1)
            m = fmaxf(m, __shfl_xor_sync(0xffffffffu, m, off));
        float s = 0.f;
#pragma unroll
        for (int k2 = 0; k2 < 4; k2++) {
            vals[k2].x = __expf(vals[k2].x - m);
            vals[k2].y = __expf(vals[k2].y - m);
            vals[k2].z = __expf(vals[k2].z - m);
            vals[k2].w = __expf(vals[k2].w - m);
            s += (vals[k2].x + vals[k2].y) + (vals[k2].z + vals[k2].w);
            pr[lane + 32 * k2] = vals[k2];
        }
#pragma unroll
        for (int off = 16; off; off >>= 1)
            s += __shfl_xor_sync(0xffffffffu, s, off);
        if (lane == 0) inv_s[ii][h] = 1.0f / s;
    }
    __syncthreads();

    // ---- attn@v: v streamed once, 4 i's accumulated together ----
#pragma unroll
    for (int rr = 0; rr < 8; rr++) {
        int row = warp * 8 + rr;             // 0..127
        int h = row >> 5;
        const float4* vr = (const float4*)(g_qkv + (2 * HID + row) * N);
        float acc[4] = {};
#pragma unroll
        for (int k2 = 0; k2 < 4; k2++) {
            float4 v4 = vr[lane + 32 * k2];
#pragma unroll
            for (int ii = 0; ii < 4; ii++) {
                float4 p4 = ((const float4*)&ps[ii][h][0])[lane + 32 * k2];
                acc[ii] = fmaf(v4.x, p4.x, acc[ii]);
                acc[ii] = fmaf(v4.y, p4.y, acc[ii]);
                acc[ii] = fmaf(v4.z, p4.z, acc[ii]);
                acc[ii] = fmaf(v4.w, p4.w, acc[ii]);
            }
        }
#pragma unroll
        for (int off = 16; off; off >>= 1)
#pragma unroll
            for (int ii = 0; ii < 4; ii++)
                acc[ii] += __shfl_xor_sync(0xffffffffu, acc[ii], off);
        if (lane == 0)
#pragma unroll
            for (int ii = 0; ii < 4; ii++)
                avs[ii][row] = acc[ii] * inv_s[ii][h];
    }
    __syncthreads();

    // ---- projection for the 4 i's ----
#pragma unroll
    for (int rr = 0; rr < 8; rr++) {
        int o = warp * 8 + rr;               // 0..127
        float4 w4 = ((const float4*)(w_out + o * HID))[lane];
        float acc[4];
#pragma unroll
        for (int ii = 0; ii < 4; ii++) {
            float4 a4 = ((const float4*)&avs[ii][0])[lane];
            acc[ii] = w4.x * a4.x + w4.y * a4.y + w4.z * a4.z + w4.w * a4.w;
        }
#pragma unroll
        for (int off = 16; off; off >>= 1)
#pragma unroll
            for (int ii = 0; ii < 4; ii++)
                acc[ii] += __shfl_xor_sync(0xffffffffu, acc[ii], off);
        if (lane == 0) {
            float bv = b_out[o];
#pragma unroll
            for (int ii = 0; ii < 4; ii++)
                out[o * N + i0 + ii] = acc[ii] + bv;
        }
    }
}

// ---------------------------------------------------------------------------
extern "C" void kernel_launch(void* const* d_in, const int* in_sizes, int n_in,
                              void* d_out, int out_size) {
    const float* x         = (const float*)d_in[0];   // (1,128,512)
    const float* indicator = (const float*)d_in[1];   // (1,5,512,512)
    const float* w_qkv     = (const float*)d_in[2];   // (384,128)
    const float* w_ind     = (const float*)d_in[3];   // (256,5)
    const float* w_out     = (const float*)d_in[4];   // (128,128)
    const float* b_out     = (const float*)d_in[5];   // (128,)
    float* out             = (float*)d_out;           // (1,128,512)

    float* qkv;  cudaGetSymbolAddress((void**)&qkv, g_qkv);

    k_qkv<<<dim3(16, 12), 256>>>(w_qkv, x, w_ind, qkv);   // qkv + A2/B3/W4
    k_qk<<<dim3(8, 8, 4), 256>>>();                        // raw q.k
    k_fused<<<N / 4, 512>>>(indicator, w_out, b_out, out); // sim+softmax+av+proj
}